// round 16
// baseline (speedup 1.0000x reference)
#include <cuda_runtime.h>
#include <math.h>
#include <stdint.h>

#define IMG_H 240
#define IMG_W 320
#define NV 12288
#define NF 4096
#define NCH 11
#define TW 16          // tile width
#define TH 8           // tile height
#define NT (TW * TH)   // 128 threads
#define CHF 128        // faces per smem chunk
#define NCHK (NF / CHF)

// ---------------- device scratch (no allocations allowed) ----------------
__device__ float g_vn[NV * 3];
__device__ float g_px[NV], g_py[NV], g_pz[NV];
__device__ float g_iw[NV], g_wcl[NV];
__device__ float g_vcol[NV * NCH];

// face data in ORIGINAL order (resolve uses these)
__device__ float4 g_hA[NF];   // bx, by, cx, cy   (NaN if invalid)
__device__ float4 g_hB[NF];   // d0x, d0y, d1x, d1y
__device__ float4 g_hC[NF];   // inv_area, z0, z1, z2
__device__ float4 g_iw4[NF];  // iw0, iw1, iw2 (resolve only)
__device__ float  g_zmin[NF];
__device__ int    g_bucket[NF];

// sorted (front-to-back by zmin) copies for the raster hot loop
__device__ float4 g_sA[NF], g_sB[NF], g_sC[NF];
__device__ int    g_sI[NF];          // sorted -> original index
__device__ float  g_szmin[NF];

__device__ unsigned int g_zlo, g_zhi;     // ford(zmin) range over valid faces
__device__ int g_hist[256], g_off[256];
__device__ float g_chmin[NCHK], g_sufmin[NCHK];

__device__ unsigned long long g_zkey[IMG_H * IMG_W];

struct Proj { float m[16]; };

__device__ __forceinline__ unsigned int ford(float d) {
    unsigned int b = __float_as_uint(d);
    return (b & 0x80000000u) ? ~b : (b | 0x80000000u);   // monotone float->uint
}

// ---------------- kernels ----------------
__global__ void k_facenorm(const float* __restrict__ verts,
                           const int* __restrict__ faces) {
    int f = blockIdx.x * blockDim.x + threadIdx.x;
    if (f >= NF) return;
    int i0 = faces[3 * f + 0], i1 = faces[3 * f + 1], i2 = faces[3 * f + 2];
    float ax = verts[3 * i0], ay = verts[3 * i0 + 1], az = verts[3 * i0 + 2];
    float bx = verts[3 * i1], by = verts[3 * i1 + 1], bz = verts[3 * i1 + 2];
    float cx = verts[3 * i2], cy = verts[3 * i2 + 1], cz = verts[3 * i2 + 2];
    float e1x = bx - ax, e1y = by - ay, e1z = bz - az;
    float e2x = cx - ax, e2y = cy - ay, e2z = cz - az;
    float nx = e1y * e2z - e1z * e2y;
    float ny = e1z * e2x - e1x * e2z;
    float nz = e1x * e2y - e1y * e2x;
    float nrm = sqrtf(nx * nx + ny * ny + nz * nz);
    nrm = fmaxf(nrm, 1e-12f);
    nx /= nrm; ny /= nrm; nz /= nrm;
    atomicAdd(&g_vn[3 * i0 + 0], nx); atomicAdd(&g_vn[3 * i0 + 1], ny); atomicAdd(&g_vn[3 * i0 + 2], nz);
    atomicAdd(&g_vn[3 * i1 + 0], nx); atomicAdd(&g_vn[3 * i1 + 1], ny); atomicAdd(&g_vn[3 * i1 + 2], nz);
    atomicAdd(&g_vn[3 * i2 + 0], nx); atomicAdd(&g_vn[3 * i2 + 1], ny); atomicAdd(&g_vn[3 * i2 + 2], nz);
}

__global__ void k_vertex(const float* __restrict__ verts,
                         const float* __restrict__ pose, Proj P) {
    int v = blockIdx.x * blockDim.x + threadIdx.x;
    if (v >= NV) return;
    float x = verts[3 * v], y = verts[3 * v + 1], z = verts[3 * v + 2];
    float p[16];
    #pragma unroll
    for (int i = 0; i < 16; i++) p[i] = pose[i];

    float wx = p[0] * x + p[1] * y + p[2]  * z + p[3];
    float wy = p[4] * x + p[5] * y + p[6]  * z + p[7];
    float wz = p[8] * x + p[9] * y + p[10] * z + p[11];
    float cam[4];
    cam[0] = wx; cam[1] = -wy; cam[2] = -wz;
    cam[3] = p[12] * x + p[13] * y + p[14] * z + p[15];
    float clip[4];
    #pragma unroll
    for (int j = 0; j < 4; j++) {
        clip[j] = P.m[4 * j + 0] * cam[0] + P.m[4 * j + 1] * cam[1]
                + P.m[4 * j + 2] * cam[2] + P.m[4 * j + 3] * cam[3];
    }
    float wc = clip[3];
    float denw = (fabsf(wc) > 1e-9f) ? wc : 1e-9f;
    float iw = 1.0f / denw;
    float n0 = clip[0] * iw, n1 = clip[1] * iw, n2 = clip[2] * iw;
    g_px[v]  = (n0 + 1.0f) * 0.5f * (float)IMG_W;
    g_py[v]  = (1.0f - n1) * 0.5f * (float)IMG_H;
    g_pz[v]  = n2;
    g_iw[v]  = iw;
    g_wcl[v] = wc;

    float vx = g_vn[3 * v], vy = g_vn[3 * v + 1], vz = g_vn[3 * v + 2];
    float nn = sqrtf(vx * vx + vy * vy + vz * vz);
    nn = fmaxf(nn, 1e-12f);
    vx /= nn; vy /= nn; vz /= nn;

    float* col = &g_vcol[v * NCH];
    col[0] = 1.0f;
    col[1] = wx; col[2] = wy; col[3] = wz;
    col[4] = vx; col[5] = vy; col[6] = vz;
    col[7] = x;  col[8] = y;  col[9] = z; col[10] = 1.0f;
}

__global__ void k_facesetup(const int* __restrict__ faces) {
    int f = blockIdx.x * blockDim.x + threadIdx.x;
    if (f >= NF) return;
    int i0 = faces[3 * f + 0], i1 = faces[3 * f + 1], i2 = faces[3 * f + 2];
    float ax = g_px[i0], ay = g_py[i0];
    float bx = g_px[i1], by = g_py[i1];
    float cx = g_px[i2], cy = g_py[i2];
    bool wok = (g_wcl[i0] > 1e-6f) && (g_wcl[i1] > 1e-6f) && (g_wcl[i2] > 1e-6f);
    float area = (bx - ax) * (cy - ay) - (by - ay) * (cx - ax);
    bool areaok = fabsf(area) > 1e-12f;
    float inv_area = 1.0f / (areaok ? area : 1e-12f);
    bool valid = areaok && wok;

    float nanf_ = __int_as_float(0x7fc00000);
    g_hA[f] = valid ? make_float4(bx, by, cx, cy)
                    : make_float4(nanf_, nanf_, nanf_, nanf_);
    g_hB[f] = make_float4(cy - by, cx - bx, ay - cy, ax - cx);
    float z0 = valid ? g_pz[i0] : 3e9f;
    float z1 = valid ? g_pz[i1] : 3e9f;
    float z2 = valid ? g_pz[i2] : 3e9f;
    g_hC[f] = make_float4(valid ? inv_area : 0.0f, z0, z1, z2);
    g_iw4[f] = make_float4(g_iw[i0], g_iw[i1], g_iw[i2], 0.0f);

    float zmin = fminf(z0, fminf(z1, z2));
    g_zmin[f] = zmin;
    if (valid) {
        unsigned u = ford(zmin);
        atomicMin(&g_zlo, u);
        atomicMax(&g_zhi, u);
    }
}

__global__ void k_hist() {
    int f = blockIdx.x * blockDim.x + threadIdx.x;
    if (f >= NF) return;
    unsigned lo = g_zlo, hi = g_zhi;
    unsigned span = (hi > lo) ? (hi - lo) : 1u;
    unsigned u = ford(g_zmin[f]);
    int b;
    if (u <= lo) b = 0;
    else if (u >= hi) b = 255;
    else b = (int)(((unsigned long long)(u - lo) * 256ull) / ((unsigned long long)span + 1ull));
    if (b > 255) b = 255;
    g_bucket[f] = b;
    atomicAdd(&g_hist[b], 1);
}

__global__ void k_scan() {   // 1 block, 256 threads: exclusive prefix sum
    __shared__ int s[256];
    int t = threadIdx.x;
    s[t] = g_hist[t];
    __syncthreads();
    int v = s[t];
    for (int o = 1; o < 256; o <<= 1) {
        int add = (t >= o) ? s[t - o] : 0;
        __syncthreads();
        s[t] = v + add;
        v = s[t];
        __syncthreads();
    }
    g_off[t] = v - g_hist[t];   // exclusive
}

__global__ void k_scatter() {
    int f = blockIdx.x * blockDim.x + threadIdx.x;
    if (f >= NF) return;
    int b = g_bucket[f];
    int pos = atomicAdd(&g_off[b], 1);
    g_sA[pos] = g_hA[f];
    g_sB[pos] = g_hB[f];
    g_sC[pos] = g_hC[f];
    g_sI[pos] = f;
    g_szmin[pos] = g_zmin[f];
}

__global__ void k_chunkmin() {   // 1 block, 1024 threads = 32 warps = NCHK chunks
    __shared__ float chm[NCHK];
    int w = threadIdx.x >> 5, lane = threadIdx.x & 31;
    float mn = 3e9f;
    #pragma unroll
    for (int k = 0; k < CHF / 32; k++)
        mn = fminf(mn, g_szmin[w * CHF + k * 32 + lane]);
    #pragma unroll
    for (int o = 16; o >= 1; o >>= 1)
        mn = fminf(mn, __shfl_xor_sync(0xffffffffu, mn, o));
    if (lane == 0) chm[w] = mn;
    __syncthreads();
    if (threadIdx.x == 0) {
        float suf = 3e9f;
        for (int c = NCHK - 1; c >= 0; c--) {
            g_chmin[c] = chm[c];
            suf = fminf(suf, chm[c]);
            g_sufmin[c] = suf;
        }
    }
}

__global__ __launch_bounds__(NT) void k_raster() {
    __shared__ float4 sA[CHF], sB[CHF], sC[CHF];
    __shared__ int    sI[CHF];

    int tx = threadIdx.x, ty = threadIdx.y;
    int x = blockIdx.x * TW + tx;
    int y = blockIdx.y * TH + ty;
    float X = (float)x + 0.5f, Y = (float)y + 0.5f;
    int tid = ty * TW + tx;
    int lane = tid & 31;
    int warp = tid >> 5;          // warp covers rows {2w, 2w+1} of the tile

    float xlo = (float)(blockIdx.x * TW) + 0.5f - 1.0f;
    float xhi = xlo + (float)(TW - 1) + 2.0f;
    float ylo = (float)(blockIdx.y * TH + warp * 2) + 0.5f - 1.0f;
    float yhi = ylo + 1.0f + 2.0f;

    float best = 1e9f;
    int bf = -1;

    for (int chunk = 0; chunk < NCHK; chunk++) {
        // warp-uniform stale upper bound on best (conservative => exact)
        float bm = best;
        #pragma unroll
        for (int o = 16; o >= 1; o >>= 1)
            bm = fmaxf(bm, __shfl_xor_sync(0xffffffffu, bm, o));
        bm += 0.01f;

        // front-to-back order: if no remaining face can win for ANY warp, stop
        int done = (__ldg(&g_sufmin[chunk]) > bm);
        if (__syncthreads_and(done)) break;

        int base = chunk * CHF;
        sA[tid] = g_sA[base + tid];
        sB[tid] = g_sB[base + tid];
        sC[tid] = g_sC[base + tid];
        sI[tid] = g_sI[base + tid];
        __syncthreads();

        if (__ldg(&g_chmin[chunk]) <= bm) {
            #pragma unroll
            for (int sub = 0; sub < CHF; sub += 32) {
                int fj = sub + lane;
                float4 A = sA[fj], B = sB[fj], C = sC[fj];
                float ia = C.x;
                float zmin = fminf(C.y, fminf(C.z, C.w));
                float gx0 = B.x * ia, gy0 = -B.y * ia;
                float gx1 = B.z * ia, gy1 = -B.w * ia;
                float xm, ym;
                xm = (gx0 >= 0.f) ? xhi : xlo;
                ym = (gy0 >= 0.f) ? yhi : ylo;
                float E0 = ((xm - A.x) * B.x - (ym - A.y) * B.y) * ia;
                xm = (gx1 >= 0.f) ? xhi : xlo;
                ym = (gy1 >= 0.f) ? yhi : ylo;
                float E1 = ((xm - A.z) * B.z - (ym - A.w) * B.w) * ia;
                xm = (gx0 + gx1 >= 0.f) ? xlo : xhi;
                ym = (gy0 + gy1 >= 0.f) ? ylo : yhi;
                float s = ((xm - A.x) * B.x - (ym - A.y) * B.y) * ia
                        + ((xm - A.z) * B.z - (ym - A.w) * B.w) * ia;
                bool hit = (E0 >= 0.f) & (E1 >= 0.f) & (s <= 1.0f) & (zmin <= bm);

                unsigned m = __ballot_sync(0xffffffffu, hit);
                while (m) {
                    int j = sub + (__ffs(m) - 1);
                    m &= m - 1;
                    float4 Aj = sA[j], Bj = sB[j], Cj = sC[j];
                    float e0 = ((X - Aj.x) * Bj.x - (Y - Aj.y) * Bj.y) * Cj.x;
                    float e1 = ((X - Aj.z) * Bj.z - (Y - Aj.w) * Bj.w) * Cj.x;
                    float e2 = 1.0f - e0 - e1;
                    float depth = e0 * Cj.y + e1 * Cj.z + e2 * Cj.w;
                    bool inside = (e0 >= 0.0f) & (e1 >= 0.0f) & (e2 >= 0.0f)
                                & (depth >= -1.0f) & (depth <= 1.0f);
                    if (inside && depth < best) { best = depth; bf = sI[j]; }
                }
            }
        }
        __syncthreads();
    }

    if (bf >= 0) {
        unsigned long long key = ((unsigned long long)ford(best) << 32) | (unsigned)bf;
        atomicMin(&g_zkey[(size_t)y * IMG_W + x], key);
    }
}

__global__ void k_resolve(const int* __restrict__ faces, float* __restrict__ out) {
    int i = blockIdx.x * blockDim.x + threadIdx.x;
    if (i >= IMG_H * IMG_W) return;
    unsigned long long key = g_zkey[i];
    float col[NCH];
    if (key != 0xFFFFFFFFFFFFFFFFull) {
        int bf = (int)(key & 0xFFFFFFFFu);
        int x = i % IMG_W, y = i / IMG_W;
        float X = (float)x + 0.5f, Y = (float)y + 0.5f;
        float4 A = g_hA[bf], B = g_hB[bf], C = g_hC[bf], W = g_iw4[bf];
        float e0 = ((X - A.x) * B.x - (Y - A.y) * B.y) * C.x;
        float e1 = ((X - A.z) * B.z - (Y - A.w) * B.w) * C.x;
        float e2 = 1.0f - e0 - e1;
        float p0 = e0 * W.x, p1 = e1 * W.y, p2 = e2 * W.z;
        float den = p0 + p1 + p2;
        den = (fabsf(den) > 1e-12f) ? den : 1e-12f;
        float w0 = p0 / den, w1 = p1 / den, w2 = p2 / den;
        int i0 = faces[3 * bf + 0], i1 = faces[3 * bf + 1], i2 = faces[3 * bf + 2];
        const float* c0 = &g_vcol[i0 * NCH];
        const float* c1 = &g_vcol[i1 * NCH];
        const float* c2 = &g_vcol[i2 * NCH];
        #pragma unroll
        for (int c = 0; c < NCH; c++)
            col[c] = w0 * c0[c] + w1 * c1[c] + w2 * c2[c];
    } else {
        #pragma unroll
        for (int c = 0; c < NCH; c++) col[c] = 0.0f;
    }
    float* o = out + (size_t)i * NCH;
    #pragma unroll
    for (int c = 0; c < NCH; c++) o[c] = col[c];
}

// ---------------- host ----------------
static Proj build_proj_host() {
    const double fx = 286.2057, sk = 0.0, cxx = 162.6306;
    const double fy = 286.7852, cyy = 121.0245;
    const double w = IMG_W, h = IMG_H;
    const double nc = 0.1, fc = 10.0;
    double q  = -(fc + nc) / (fc - nc);
    double qn = -2.0 * fc * nc / (fc - nc);
    double m[4][4] = {
        {2.0 * fx / w, -2.0 * sk / w, (-2.0 * cxx + w) / w, 0.0},
        {0.0, -2.0 * fy / h, (-2.0 * cyy + h) / h, 0.0},
        {0.0, 0.0, q, qn},
        {0.0, 0.0, -1.0, 0.0}
    };
    for (int k = 0; k < 4; k++) m[1][k] *= -1.0;
    Proj P;
    for (int j = 0; j < 4; j++)
        for (int k = 0; k < 4; k++)
            P.m[4 * j + k] = (float)m[j][k];
    return P;
}

extern "C" void kernel_launch(void* const* d_in, const int* in_sizes, int n_in,
                              void* d_out, int out_size) {
    const float* verts = nullptr;
    const int*   faces = nullptr;
    const float* pose  = nullptr;
    for (int i = 0; i < n_in; i++) {
        if (in_sizes[i] == NV * 3)       verts = (const float*)d_in[i];
        else if (in_sizes[i] == NF * 3)  faces = (const int*)d_in[i];
        else if (in_sizes[i] == 16)      pose  = (const float*)d_in[i];
    }
    float* out = (float*)d_out;    // (1, 240, 320, 11)
    (void)out_size;

    Proj P = build_proj_host();

    void *vn_ptr, *zk_ptr, *hist_ptr, *zlo_ptr, *zhi_ptr;
    cudaGetSymbolAddress(&vn_ptr, g_vn);
    cudaGetSymbolAddress(&zk_ptr, g_zkey);
    cudaGetSymbolAddress(&hist_ptr, g_hist);
    cudaGetSymbolAddress(&zlo_ptr, g_zlo);
    cudaGetSymbolAddress(&zhi_ptr, g_zhi);
    cudaMemsetAsync(vn_ptr, 0, NV * 3 * sizeof(float));
    cudaMemsetAsync(zk_ptr, 0xFF, IMG_H * IMG_W * sizeof(unsigned long long));
    cudaMemsetAsync(hist_ptr, 0, 256 * sizeof(int));
    cudaMemsetAsync(zlo_ptr, 0xFF, sizeof(unsigned int));
    cudaMemsetAsync(zhi_ptr, 0x00, sizeof(unsigned int));

    k_facenorm<<<(NF + 127) / 128, 128>>>(verts, faces);
    k_vertex<<<(NV + 255) / 256, 256>>>(verts, pose, P);
    k_facesetup<<<(NF + 127) / 128, 128>>>(faces);
    k_hist<<<(NF + 255) / 256, 256>>>();
    k_scan<<<1, 256>>>();
    k_scatter<<<(NF + 255) / 256, 256>>>();
    k_chunkmin<<<1, 1024>>>();
    dim3 grid(IMG_W / TW, IMG_H / TH);
    dim3 blk(TW, TH);
    k_raster<<<grid, blk>>>();
    k_resolve<<<(IMG_H * IMG_W + 255) / 256, 256>>>(faces, out);
}